// round 5
// baseline (speedup 1.0000x reference)
#include <cuda_runtime.h>
#include <cstdint>
#include <cstddef>

#define NPAIRS 50000
#define NFEAT  1140
#define NEDGE  38

#define BM 128
#define BN 128
#define BK 16
#define KT ((NFEAT + BK - 1) / BK)   /* 72 K-stages (K padded to 1152 with zeros) */
#define JT ((NFEAT + BN - 1) / BN)   /* 9 j-tiles */
#define AS 20    /* A smem row stride in floats: (20g+t)%32 distinct -> conflict-free */
#define BS 136   /* B smem row stride in floats: (8t+g)%32 distinct  -> conflict-free */

// fp32 -> tf32 with round-to-nearest (halves the rounding error vs HW truncation)
__device__ __forceinline__ uint32_t f2tf(float f) {
    uint32_t u;
    asm("cvt.rna.tf32.f32 %0, %1;" : "=r"(u) : "f"(f));
    return u;
}

__device__ __forceinline__ void mma_tf32(float* c, const uint32_t* a, const uint32_t* b) {
    asm volatile(
        "mma.sync.aligned.m16n8k8.row.col.f32.tf32.tf32.f32 "
        "{%0,%1,%2,%3}, {%4,%5,%6,%7}, {%8,%9}, {%0,%1,%2,%3};"
        : "+f"(c[0]), "+f"(c[1]), "+f"(c[2]), "+f"(c[3])
        : "r"(a[0]), "r"(a[1]), "r"(a[2]), "r"(a[3]),
          "r"(b[0]), "r"(b[1]));
}

// 16B cp.async with zero-fill predication (src-size = 0 -> dst zero-filled)
__device__ __forceinline__ void cp16(float* smem_dst, const float* gsrc, bool pred) {
    uint32_t saddr = (uint32_t)__cvta_generic_to_shared(smem_dst);
    int sz = pred ? 16 : 0;
    asm volatile("cp.async.cg.shared.global [%0], [%1], 16, %2;\n"
                 :: "r"(saddr), "l"(gsrc), "r"(sz));
}

// Load one K-stage: A = start tile [BM x BK], B = W tile [BK x BN] (k-major rows)
__device__ __forceinline__ void load_stage(
    float* Adst, float* Bdst,
    const float* __restrict__ start_emb, const float* __restrict__ We,
    int n0, int j0, int k0, int tid)
{
    // A: 128 rows x 4 float4; thread -> (m = tid/4 + r*64, kv = (tid%4)*4)
    #pragma unroll
    for (int r = 0; r < 2; r++) {
        int m  = (tid >> 2) + r * 64;
        int kv = (tid & 3) * 4;
        bool p = (n0 + m < NPAIRS) && (k0 + kv < NFEAT);
        const float* src = p ? (start_emb + (size_t)(n0 + m) * NFEAT + k0 + kv) : start_emb;
        cp16(Adst + m * AS + kv, src, p);
    }
    // B: 16 rows x 32 float4; thread -> (i = tid/32 + r*8, jv = (tid%32)*4)
    #pragma unroll
    for (int r = 0; r < 2; r++) {
        int i  = (tid >> 5) + r * 8;
        int jv = (tid & 31) * 4;
        bool p = (k0 + i < NFEAT) && (j0 + jv < NFEAT);
        const float* src = p ? (We + (size_t)(k0 + i) * NFEAT + j0 + jv) : We;
        cp16(Bdst + i * BS + jv, src, p);
    }
}

__global__ void __launch_bounds__(256, 2)
kway_fused(const float* __restrict__ start_emb,
           const float* __restrict__ end_emb,
           const float* __restrict__ weights,
           float* __restrict__ out)
{
    __shared__ __align__(16) float Asm[2][BM * AS];
    __shared__ __align__(16) float Bsm[2][BK * BS];
    __shared__ float osum[BM];

    const int tid    = threadIdx.x;
    const int lane   = tid & 31;
    const int wid    = tid >> 5;
    const int warp_m = wid & 3;   // 4 strips of 32 rows
    const int warp_n = wid >> 2;  // 2 strips of 64 cols
    const int g = lane >> 2;      // groupID
    const int t = lane & 3;       // threadID_in_group

    const int n0 = blockIdx.x * BM;
    const int e  = blockIdx.y;

    const float* We = weights + (size_t)e * NFEAT * NFEAT;

    // per-thread running dot for 4 owned output rows (mt x row-half)
    float rowsum[2][2] = {{0.f, 0.f}, {0.f, 0.f}};

    for (int r = tid; r < BM; r += 256) osum[r] = 0.f;

    for (int jt = 0; jt < JT; jt++) {
        const int j0 = jt * BN;

        float acc[2][8][4];
        #pragma unroll
        for (int mt = 0; mt < 2; mt++)
            #pragma unroll
            for (int nt = 0; nt < 8; nt++)
                #pragma unroll
                for (int q = 0; q < 4; q++) acc[mt][nt][q] = 0.f;

        load_stage(Asm[0], Bsm[0], start_emb, We, n0, j0, 0, tid);
        asm volatile("cp.async.commit_group;\n" ::: "memory");

        for (int kt = 0; kt < KT; kt++) {
            const int buf = kt & 1;
            if (kt + 1 < KT)
                load_stage(Asm[buf ^ 1], Bsm[buf ^ 1], start_emb, We, n0, j0,
                           (kt + 1) * BK, tid);
            asm volatile("cp.async.commit_group;\n" ::: "memory");
            asm volatile("cp.async.wait_group 1;\n" ::: "memory");
            __syncthreads();

            const float* A = Asm[buf];
            const float* B = Bsm[buf];
            #pragma unroll
            for (int kk = 0; kk < 2; kk++) {
                const int ks = kk * 8 + t;
                uint32_t af[2][4];
                #pragma unroll
                for (int mt = 0; mt < 2; mt++) {
                    const int rb = (warp_m * 32 + mt * 16 + g) * AS;
                    af[mt][0] = f2tf(A[rb + ks]);
                    af[mt][1] = f2tf(A[rb + 8 * AS + ks]);
                    af[mt][2] = f2tf(A[rb + ks + 4]);
                    af[mt][3] = f2tf(A[rb + 8 * AS + ks + 4]);
                }
                uint32_t bfr[8][2];
                #pragma unroll
                for (int nt = 0; nt < 8; nt++) {
                    const int col = warp_n * 64 + nt * 8 + g;
                    bfr[nt][0] = f2tf(B[ks * BS + col]);
                    bfr[nt][1] = f2tf(B[(ks + 4) * BS + col]);
                }
                #pragma unroll
                for (int mt = 0; mt < 2; mt++)
                    #pragma unroll
                    for (int nt = 0; nt < 8; nt++)
                        mma_tf32(acc[mt][nt], af[mt], bfr[nt]);
            }
            __syncthreads();
        }

        // Epilogue: out-partial = sum_j q[row,j] * end[row,j], end stays fp32
        #pragma unroll
        for (int mt = 0; mt < 2; mt++) {
            #pragma unroll
            for (int rh = 0; rh < 2; rh++) {
                const int row = n0 + warp_m * 32 + mt * 16 + rh * 8 + g;
                if (row < NPAIRS) {
                    const float* er = end_emb + (size_t)row * NFEAT;
                    float s = 0.f;
                    #pragma unroll
                    for (int nt = 0; nt < 8; nt++) {
                        const int j = j0 + warp_n * 64 + nt * 8 + 2 * t;
                        if (j < NFEAT) {
                            float2 ev = *reinterpret_cast<const float2*>(er + j);
                            s += acc[mt][nt][rh * 2]     * ev.x
                               + acc[mt][nt][rh * 2 + 1] * ev.y;
                        }
                    }
                    rowsum[mt][rh] += s;
                }
            }
        }
    }

    // Reduce across the t-quad (lanes sharing a row), then across the two
    // warp_n strips via shared atomics (exactly 2 adds per address -> a+b
    // is bitwise commutative -> deterministic).
    #pragma unroll
    for (int mt = 0; mt < 2; mt++) {
        #pragma unroll
        for (int rh = 0; rh < 2; rh++) {
            float s = rowsum[mt][rh];
            s += __shfl_xor_sync(0xffffffffu, s, 1);
            s += __shfl_xor_sync(0xffffffffu, s, 2);
            if (t == 0) {
                const int rl = warp_m * 32 + mt * 16 + rh * 8 + g;
                atomicAdd(&osum[rl], s);
            }
        }
    }
    __syncthreads();

    for (int r = tid; r < BM; r += 256) {
        const int row = n0 + r;
        if (row < NPAIRS) out[(size_t)e * NPAIRS + row] = osum[r];
    }
}

extern "C" void kernel_launch(void* const* d_in, const int* in_sizes, int n_in,
                              void* d_out, int out_size) {
    (void)in_sizes; (void)n_in; (void)out_size;
    const float* start_emb = (const float*)d_in[0];
    const float* end_emb   = (const float*)d_in[1];
    const float* weights   = (const float*)d_in[2];
    float* out = (float*)d_out;

    dim3 grid((NPAIRS + BM - 1) / BM, NEDGE, 1);  // (391, 38)
    kway_fused<<<grid, 256>>>(start_emb, end_emb, weights, out);
}

// round 12
// speedup vs baseline: 2.3389x; 2.3389x over previous
#include <cuda_runtime.h>
#include <cuda_fp16.h>
#include <cstdint>
#include <cstddef>

#define NPAIRS 50000
#define NFEAT  1140
#define NEDGE  38

#define NT16   (NPAIRS / 16)            /* 3125 A row-tiles (exact)        */
#define KT16   72                       /* k16 tiles: K padded to 1152     */
#define NP16   72                       /* j 16-col pair-tiles: j pad 1152 */
#define BM     128
#define BN     128
#define NSTG   36                       /* stages of BK=32 (2 k16 each)    */
#define JT     9                        /* j passes of 128                 */
#define NTILES ((NPAIRS + BM - 1) / BM) /* 391                             */

// Fragment-major fp16 scratch (device bss — no runtime allocation).
// A tile [16m x 16k] = 128 u32 ordered [lane][4 regs a0..a3].
// B tile [16k x 16j] = 128 u32 ordered [lane][4 regs b0,b1,b0',b1'].
__device__ __align__(256) uint32_t g_a[(size_t)NT16 * KT16 * 128];          // 115.2 MB
__device__ __align__(256) uint32_t g_b[(size_t)NEDGE * NP16 * KT16 * 128];  // 100.8 MB

__device__ __forceinline__ void cp16z(uint32_t sdst, const void* gsrc, bool pred) {
    int sz = pred ? 16 : 0;
    asm volatile("cp.async.cg.shared.global [%0], [%1], 16, %2;\n"
                 :: "r"(sdst), "l"(gsrc), "r"(sz));
}

__device__ __forceinline__ void mma16(float* c, uint4 a, uint32_t b0, uint32_t b1) {
    asm volatile(
        "mma.sync.aligned.m16n8k16.row.col.f32.f16.f16.f32 "
        "{%0,%1,%2,%3}, {%4,%5,%6,%7}, {%8,%9}, {%0,%1,%2,%3};"
        : "+f"(c[0]), "+f"(c[1]), "+f"(c[2]), "+f"(c[3])
        : "r"(a.x), "r"(a.y), "r"(a.z), "r"(a.w), "r"(b0), "r"(b1));
}

__device__ __forceinline__ uint32_t pack2(float lo, float hi) {
    __half l = __float2half_rn(lo), h = __float2half_rn(hi);
    return ((uint32_t)__half_as_ushort(h) << 16) | (uint32_t)__half_as_ushort(l);
}

// ---------------- prologue: convert + fragment-swizzle (every launch) ------

// A: start[n][k] -> fp16 fragments. reg r: row = g + (r&1)*8, col = 2t + (r>>1)*8.
__global__ void conv_a_k(const float* __restrict__ src) {
    __shared__ float s[16][65];
    const int nt = blockIdx.x, kb = blockIdx.y;   // kb: 0..17 (64 k each)
    const int tid = threadIdx.x;
    const int k0 = kb * 64;
    #pragma unroll
    for (int i = 0; i < 4; i++) {
        int idx = tid + i * 256;
        int row = idx >> 6, col = idx & 63;
        float v = 0.f;
        if (k0 + col < NFEAT)
            v = src[(size_t)(nt * 16 + row) * NFEAT + k0 + col];
        s[row][col] = v;
    }
    __syncthreads();
    #pragma unroll
    for (int r = 0; r < 2; r++) {
        int o = tid * 2 + r;                       // 512 u32 outputs
        int ktl = o >> 7, rem = o & 127;           // ktl 0..3
        int lane = rem >> 2, reg = rem & 3;
        int g = lane >> 2, t = lane & 3;
        int row = g + (reg & 1) * 8;
        int col = ktl * 16 + 2 * t + (reg >> 1) * 8;
        g_a[((size_t)nt * KT16 + kb * 4 + ktl) * 128 + rem] =
            pack2(s[row][col], s[row][col + 1]);
    }
}

// B: W[e][k][j] -> fp16 fragments (col-major n). reg r:
//   k = ktl*16 + 2t + (r&1)*8, j = g + (r>>1)*8; pair {W[k][j], W[k+1][j]}.
// R11 bug fixed here: block owns 4 k16-tiles = 512 u32 (was writing 1024,
// ktl reached 7 -> kb*4+ktl up to 75 -> OOB write past g_b).
__global__ void conv_b_k(const float* __restrict__ w) {
    __shared__ float sb[64][17];
    const int kb = blockIdx.x, np = blockIdx.y, e = blockIdx.z;
    const int tid = threadIdx.x;
    const int k0 = kb * 64, j0 = np * 16;
    #pragma unroll
    for (int i = 0; i < 4; i++) {
        int idx = tid + i * 256;
        int row = idx >> 4, col = idx & 15;
        float v = 0.f;
        if (k0 + row < NFEAT && j0 + col < NFEAT)
            v = w[((size_t)e * NFEAT + k0 + row) * NFEAT + j0 + col];
        sb[row][col] = v;
    }
    __syncthreads();
    #pragma unroll
    for (int r = 0; r < 2; r++) {
        int o = tid * 2 + r;                       // 512 u32 outputs
        int ktl = o >> 7, rem = o & 127;           // ktl 0..3
        int lane = rem >> 2, reg = rem & 3;
        int g = lane >> 2, t = lane & 3;
        int krow = ktl * 16 + 2 * t + (reg & 1) * 8;
        int jcol = g + (reg >> 1) * 8;
        g_b[(((size_t)e * NP16 + np) * KT16 + kb * 4 + ktl) * 128 + rem] =
            pack2(sb[krow][jcol], sb[krow + 1][jcol]);
    }
}

// ---------------- main HMMA kernel ------------------------------------------

__global__ void __launch_bounds__(256, 2)
kway_hmma(const float* __restrict__ end_emb, float* __restrict__ out)
{
    __shared__ __align__(16) uint32_t Abuf[2][2048];   // [buf][mt(8)][ksub(2)][lane(32)][4]
    __shared__ __align__(16) uint32_t Bbuf[2][2048];   // [buf][np(8)][ksub(2)][lane(32)][4]
    __shared__ float osum[BM];

    const int tid  = threadIdx.x;
    const int lane = tid & 31;
    const int wid  = tid >> 5;
    const int warp_m = wid & 3;     // 4 strips of 32 rows
    const int warp_n = wid >> 2;    // 2 strips of 64 j
    const int g = lane >> 2;
    const int t = lane & 3;

    const int n0  = blockIdx.x * BM;
    const int e   = blockIdx.y;
    const int nt0 = n0 >> 4;
    const uint32_t* __restrict__ Bg = g_b + (size_t)e * NP16 * KT16 * 128;

    const uint32_t a_sm = (uint32_t)__cvta_generic_to_shared(Abuf);
    const uint32_t b_sm = (uint32_t)__cvta_generic_to_shared(Bbuf);

    float rowsum[2][2] = {{0.f, 0.f}, {0.f, 0.f}};
    for (int r = tid; r < BM; r += 256) osum[r] = 0.f;

    for (int jt = 0; jt < JT; jt++) {
        const int np0 = jt * 8;

        float acc[2][8][4];
        #pragma unroll
        for (int mt = 0; mt < 2; mt++)
            #pragma unroll
            for (int nt = 0; nt < 8; nt++)
                #pragma unroll
                for (int q = 0; q < 4; q++) acc[mt][nt][q] = 0.f;

        // ---- stage loader ----
        #define LOAD_STAGE(BUF, KT2)                                            \
        do {                                                                    \
            const int _k16 = (KT2) * 2;                                         \
            _Pragma("unroll")                                                   \
            for (int _i = 0; _i < 2; _i++) {                                    \
                int _c = tid + _i * 256;                                        \
                int _mt = _c >> 6, _rem = _c & 63;                              \
                int _tile = nt0 + _mt;                                          \
                bool _p = _tile < NT16;                                         \
                const uint32_t* _src =                                          \
                    g_a + ((size_t)(_p ? _tile : 0) * KT16 + _k16) * 128        \
                        + _rem * 4;                                             \
                cp16z(a_sm + ((BUF) * 2048 + _mt * 256 + _rem * 4) * 4,         \
                      _src, _p);                                                \
            }                                                                   \
            _Pragma("unroll")                                                   \
            for (int _i = 0; _i < 2; _i++) {                                    \
                int _c = tid + _i * 256;                                        \
                int _np = _c >> 6, _rem = _c & 63;                              \
                const uint32_t* _src =                                          \
                    Bg + ((size_t)(np0 + _np) * KT16 + _k16) * 128 + _rem * 4;  \
                cp16z(b_sm + ((BUF) * 2048 + _np * 256 + _rem * 4) * 4,         \
                      _src, true);                                              \
            }                                                                   \
        } while (0)

        LOAD_STAGE(0, 0);
        asm volatile("cp.async.commit_group;\n" ::: "memory");

        for (int kt = 0; kt < NSTG; kt++) {
            const int buf = kt & 1;
            if (kt + 1 < NSTG) LOAD_STAGE(buf ^ 1, kt + 1);
            asm volatile("cp.async.commit_group;\n" ::: "memory");
            asm volatile("cp.async.wait_group 1;\n" ::: "memory");
            __syncthreads();

            #pragma unroll
            for (int ksub = 0; ksub < 2; ksub++) {
                uint4 a0 = *reinterpret_cast<const uint4*>(
                    &Abuf[buf][(warp_m * 2 + 0) * 256 + ksub * 128 + lane * 4]);
                uint4 a1 = *reinterpret_cast<const uint4*>(
                    &Abuf[buf][(warp_m * 2 + 1) * 256 + ksub * 128 + lane * 4]);
                #pragma unroll
                for (int np = 0; np < 4; np++) {
                    uint4 b = *reinterpret_cast<const uint4*>(
                        &Bbuf[buf][(warp_n * 4 + np) * 256 + ksub * 128 + lane * 4]);
                    mma16(acc[0][np * 2 + 0], a0, b.x, b.y);
                    mma16(acc[0][np * 2 + 1], a0, b.z, b.w);
                    mma16(acc[1][np * 2 + 0], a1, b.x, b.y);
                    mma16(acc[1][np * 2 + 1], a1, b.z, b.w);
                }
            }
            __syncthreads();
        }
        #undef LOAD_STAGE

        // ---- epilogue: fp32 dot with end_emb, accumulate per owned row ----
        const int j0 = jt * BN;
        #pragma unroll
        for (int mt = 0; mt < 2; mt++) {
            #pragma unroll
            for (int rh = 0; rh < 2; rh++) {
                const int row = n0 + warp_m * 32 + mt * 16 + rh * 8 + g;
                if (row < NPAIRS) {
                    const float* er = end_emb + (size_t)row * NFEAT;
                    float s = 0.f;
                    #pragma unroll
                    for (int nt = 0; nt < 8; nt++) {
                        const int j = j0 + warp_n * 64 + nt * 8 + 2 * t;
                        if (j < NFEAT) {
                            float2 ev = *reinterpret_cast<const float2*>(er + j);
                            s += acc[mt][nt][rh * 2]     * ev.x
                               + acc[mt][nt][rh * 2 + 1] * ev.y;
                        }
                    }
                    rowsum[mt][rh] += s;
                }
            }
        }
    }

    // Reduce across t-quad, then across the 2 warp_n strips (2 deterministic
    // shared atomics per address — commutative, bit-stable).
    #pragma unroll
    for (int mt = 0; mt < 2; mt++) {
        #pragma unroll
        for (int rh = 0; rh < 2; rh++) {
            float s = rowsum[mt][rh];
            s += __shfl_xor_sync(0xffffffffu, s, 1);
            s += __shfl_xor_sync(0xffffffffu, s, 2);
            if (t == 0) {
                const int rl = warp_m * 32 + mt * 16 + rh * 8 + g;
                atomicAdd(&osum[rl], s);
            }
        }
    }
    __syncthreads();

    for (int r = tid; r < BM; r += 256) {
        const int row = n0 + r;
        if (row < NPAIRS) out[(size_t)e * NPAIRS + row] = osum[r];
    }
}

extern "C" void kernel_launch(void* const* d_in, const int* in_sizes, int n_in,
                              void* d_out, int out_size) {
    (void)in_sizes; (void)n_in; (void)out_size;
    const float* start_emb = (const float*)d_in[0];
    const float* end_emb   = (const float*)d_in[1];
    const float* weights   = (const float*)d_in[2];
    float* out = (float*)d_out;

    conv_a_k<<<dim3(NT16, 18), 256>>>(start_emb);
    conv_b_k<<<dim3(18, NP16, NEDGE), 256>>>(weights);

    // x = n-tile (fast), y = e (slow): a concurrent wave shares one W_e in L2
    kway_hmma<<<dim3(NTILES, NEDGE), 256>>>(end_emb, out);
}